// round 4
// baseline (speedup 1.0000x reference)
#include <cuda_runtime.h>
#include <cuda_bf16.h>
#include <cstdint>

// ----------------------------------------------------------------------------
// VQ: bf16 screening GEMM (tensor cores) + deterministic-bound candidate
//     rescore in exact fp32 reference rounding.
// inputs : d_in[0] = X [N=262144, D=128] fp32 ; d_in[1] = E [128, 1024] fp32
// outputs: d_out = [ quantized (N*D) | loss (1) | indices-as-float (N) ]
// ----------------------------------------------------------------------------

#define KCODES  1024
#define DDIM    128
#define MTILE   128
#define NCHUNK  128
#define NCHUNKS 8
#define THREADS 256
#define CAP     48

#define XSTRIDE 132            // fp32 X tile row stride (floats)
#define BSTRIDE 272            // E chunk row stride bytes (128 bf16 + 8 pad)

// SMEM layout (bytes)
#define SM_X    0                                  // 128*132*4      = 67584
#define SM_B    67584                              // 2 * 128*272    = 69632
#define SM_ESQ  137216                             // 1024 f         =  4096
#define SM_XSQ  141312                             // 128 f          =   512
#define SM_BND  141824                             // 128 f (2*B)    =   512
#define SM_CNT  142336                             // 128 int        =   512
#define SM_BEST 142848                             // 128 u64        =  1024
#define SM_CAND 143872                             // 128*48*4       = 24576
#define SM_TOTAL 168448

#define BBUF    (MTILE * BSTRIDE)                  // 34816 per buffer

// scratch globals (no cudaMalloc allowed)
__device__ double g_loss_acc;
__device__ __align__(16) float         g_esq[KCODES];
__device__ __align__(16) __nv_bfloat16 g_ET_hh[KCODES * DDIM];   // [k][d] bf16
__device__ __align__(16) float         g_ET_f32[KCODES * DDIM];  // [k][d] fp32

// ---- helpers ----------------------------------------------------------------
__device__ __forceinline__ uint32_t smem_u32(const void* p) {
    uint32_t a;
    asm("{ .reg .u64 t; cvta.to.shared.u64 t, %1; cvt.u32.u64 %0, t; }"
        : "=r"(a) : "l"(p));
    return a;
}
__device__ __forceinline__ void cp_async16(uint32_t dst, const void* src) {
    asm volatile("cp.async.cg.shared.global [%0], [%1], 16;"
                 :: "r"(dst), "l"(src) : "memory");
}
__device__ __forceinline__ void cp_commit() {
    asm volatile("cp.async.commit_group;" ::: "memory");
}
template <int N> __device__ __forceinline__ void cp_wait() {
    asm volatile("cp.async.wait_group %0;" :: "n"(N) : "memory");
}
__device__ __forceinline__ void mma16816(float* d, uint32_t a0, uint32_t a1,
                                         uint32_t a2, uint32_t a3,
                                         uint32_t b0, uint32_t b1) {
    asm volatile(
        "mma.sync.aligned.m16n8k16.row.col.f32.bf16.bf16.f32 "
        "{%0,%1,%2,%3}, {%4,%5,%6,%7}, {%8,%9}, {%0,%1,%2,%3};"
        : "+f"(d[0]), "+f"(d[1]), "+f"(d[2]), "+f"(d[3])
        : "r"(a0), "r"(a1), "r"(a2), "r"(a3), "r"(b0), "r"(b1));
}
__device__ __forceinline__ uint32_t pack_bf2(float x, float y) {
    __nv_bfloat162 v = __halves2bfloat162(__float2bfloat16(x), __float2bfloat16(y));
    return *(uint32_t*)&v;
}

// ---- prep: esq, E transpose (bf16 + fp32), zero loss ------------------------
__global__ void vq_prep_kernel(const float* __restrict__ E) {
    int k = blockIdx.x * blockDim.x + threadIdx.x;
    if (k == 0) g_loss_acc = 0.0;
    if (k >= KCODES) return;
    float s = 0.f;
#pragma unroll 8
    for (int d = 0; d < DDIM; ++d) {
        float e = E[(size_t)d * KCODES + k];
        s = fmaf(e, e, s);
        g_ET_hh[k * DDIM + d]  = __float2bfloat16(e);
        g_ET_f32[k * DDIM + d] = e;
    }
    g_esq[k] = s;
}

// ---- issue cp.async for one E chunk into buffer buf -------------------------
__device__ __forceinline__ void issue_B(char* smem, int buf, int c0, int t) {
    uint32_t base = smem_u32(smem + SM_B) + buf * BBUF;
#pragma unroll
    for (int j = 0; j < 8; ++j) {                 // 2048 16B ops / 256 threads
        int idx = t + j * THREADS;
        int r   = idx >> 4;                       // code row
        int seg = idx & 15;                       // 16B segment (16 per 256B)
        cp_async16(base + r * BSTRIDE + seg * 16,
                   g_ET_hh + (size_t)(c0 + r) * DDIM + seg * 8);
    }
    cp_commit();
}

// ---- exact fp32 rescore of one (row, code); reference rounding --------------
__device__ __forceinline__ void rescore_one(const float* Xs, int row, int code,
                                            float xsq, const float* esq_s,
                                            unsigned long long* best) {
    const float4* xr = (const float4*)&Xs[row * XSTRIDE];
    const float4* er = (const float4*)&g_ET_f32[(size_t)code * DDIM];
    float dot = 0.f;
#pragma unroll 8
    for (int i = 0; i < 32; ++i) {
        float4 xv = xr[i];
        float4 ev = __ldg(&er[i]);
        dot = fmaf(xv.x, ev.x, dot);
        dot = fmaf(xv.y, ev.y, dot);
        dot = fmaf(xv.z, ev.z, dot);
        dot = fmaf(xv.w, ev.w, dot);
    }
    float m  = __fmul_rn(2.f, dot);
    float tt = __fadd_rn(xsq, -m);
    float dd = __fadd_rn(tt, esq_s[code]);
    unsigned long long packed =
        ((unsigned long long)__float_as_uint(dd) << 32) | (unsigned)code;
    atomicMin(&best[row], packed);
}

// ---- main fused kernel ------------------------------------------------------
__global__ __launch_bounds__(THREADS, 1) void vq_main_kernel(
    const float* __restrict__ X, float* __restrict__ q_out, float* __restrict__ idx_out)
{
    extern __shared__ char smem[];
    float* Xs    = (float*)(smem + SM_X);
    float* esq_s = (float*)(smem + SM_ESQ);
    float* xsq_s = (float*)(smem + SM_XSQ);
    float* bnd_s = (float*)(smem + SM_BND);
    int*   cnt_s = (int*)(smem + SM_CNT);
    unsigned long long* best_s = (unsigned long long*)(smem + SM_BEST);
    int*   cand_s = (int*)(smem + SM_CAND);

    const int t    = threadIdx.x;
    const int w    = t >> 5;
    const int lane = t & 31;
    const int g    = lane >> 2;          // row within 8-group
    const int q    = (lane & 3) << 1;    // even col offset
    const int rowBase = blockIdx.x * MTILE;

    // prefetch first E chunk immediately
    issue_B(smem, 0, 0, t);

    // esq -> SMEM; init cnt/best
    for (int i = t; i < KCODES; i += THREADS) esq_s[i] = g_esq[i];
    if (t < MTILE) { cnt_s[t] = 0; best_s[t] = 0xFFFFFFFFFFFFFFFFull; }

    // X tile fp32 -> SMEM (coalesced)
    const float4* X4 = (const float4*)(X + (size_t)rowBase * DDIM);
#pragma unroll
    for (int i = 0; i < 16; ++i) {
        int idx = t + i * THREADS;
        int row = idx >> 5;
        int c4  = idx & 31;
        *(float4*)&Xs[row * XSTRIDE + c4 * 4] = X4[idx];
    }
    __syncthreads();

    // per-row ||x||^2 (sequential fmaf) and screening bound 2*B_row
    if (t < MTILE) {
        float s = 0.f, s1 = 0.f;
#pragma unroll 8
        for (int d = 0; d < DDIM; ++d) {
            float x = Xs[t * XSTRIDE + d];
            s  = fmaf(x, x, s);
            s1 += fabsf(x);
        }
        xsq_s[t] = s;
        // |dist_scr - dist_fp32| <= 1.2e-3 * sum|x| + slack; store 2*B
        bnd_s[t] = 2.f * (1.202e-3f * s1 + 0.004f);
    }

    // A fragments (bf16 of x) in registers, reused across chunks
    const int r0 = 16 * w + g;
    const int r1 = r0 + 8;
    uint32_t a[8][4];
#pragma unroll
    for (int ks = 0; ks < 8; ++ks) {
        int k0 = ks * 16;
        float2 f0 = *(const float2*)&Xs[r0 * XSTRIDE + k0 + q];
        float2 f1 = *(const float2*)&Xs[r1 * XSTRIDE + k0 + q];
        float2 f2 = *(const float2*)&Xs[r0 * XSTRIDE + k0 + q + 8];
        float2 f3 = *(const float2*)&Xs[r1 * XSTRIDE + k0 + q + 8];
        a[ks][0] = pack_bf2(f0.x, f0.y);
        a[ks][1] = pack_bf2(f1.x, f1.y);
        a[ks][2] = pack_bf2(f2.x, f2.y);
        a[ks][3] = pack_bf2(f3.x, f3.y);
    }
    __syncthreads();
    const float xsqA = xsq_s[r0], xsqB = xsq_s[r1];
    const float twoBA = bnd_s[r0], twoBB = bnd_s[r1];

    float rmA = 3.402823466e38f, rmB = 3.402823466e38f;

    // ---- screening loop -----------------------------------------------------
    for (int ch = 0; ch < NCHUNKS; ++ch) {
        const int buf = ch & 1;
        if (ch + 1 < NCHUNKS) {
            issue_B(smem, (ch + 1) & 1, (ch + 1) * NCHUNK, t);
            cp_wait<1>();
        } else {
            cp_wait<0>();
        }
        __syncthreads();

        const char* Bh = smem + SM_B + buf * BBUF;

        float acc[16][4];
#pragma unroll
        for (int nt = 0; nt < 16; ++nt) {
            acc[nt][0] = 0.f; acc[nt][1] = 0.f; acc[nt][2] = 0.f; acc[nt][3] = 0.f;
        }
#pragma unroll
        for (int ks = 0; ks < 8; ++ks) {
            const uint32_t a0 = a[ks][0], a1 = a[ks][1], a2 = a[ks][2], a3 = a[ks][3];
            const int koff0 = (ks * 16 + q) * 2;
            const int koff1 = (ks * 16 + q + 8) * 2;
#pragma unroll
            for (int nt = 0; nt < 16; ++nt) {
                const char* rowp = Bh + (nt * 8 + g) * BSTRIDE;
                uint32_t b0 = *(const uint32_t*)(rowp + koff0);
                uint32_t b1 = *(const uint32_t*)(rowp + koff1);
                mma16816(acc[nt], a0, a1, a2, a3, b0, b1);
            }
        }

        // fold: screened dist = esq - 2*dot ; push candidates within window
        const int cbase = ch * NCHUNK;
#pragma unroll
        for (int nt = 0; nt < 16; ++nt) {
            int cA = cbase + nt * 8 + q;
            float2 e2 = *(const float2*)&esq_s[cA];
            float tv;
            tv = fmaf(-2.f, acc[nt][0], e2.x);
            if (tv < rmA + twoBA) {
                if (tv < rmA) rmA = tv;
                int p = atomicAdd(&cnt_s[r0], 1);
                if (p < CAP) cand_s[r0 * CAP + p] = cA;
            }
            tv = fmaf(-2.f, acc[nt][1], e2.y);
            if (tv < rmA + twoBA) {
                if (tv < rmA) rmA = tv;
                int p = atomicAdd(&cnt_s[r0], 1);
                if (p < CAP) cand_s[r0 * CAP + p] = cA + 1;
            }
            tv = fmaf(-2.f, acc[nt][2], e2.x);
            if (tv < rmB + twoBB) {
                if (tv < rmB) rmB = tv;
                int p = atomicAdd(&cnt_s[r1], 1);
                if (p < CAP) cand_s[r1 * CAP + p] = cA;
            }
            tv = fmaf(-2.f, acc[nt][3], e2.y);
            if (tv < rmB + twoBB) {
                if (tv < rmB) rmB = tv;
                int p = atomicAdd(&cnt_s[r1], 1);
                if (p < CAP) cand_s[r1 * CAP + p] = cA + 1;
            }
        }
        __syncthreads();   // buffer reuse
    }

    // ---- exact rescore of candidates ---------------------------------------
    {
        const int row  = t & 127;
        const int half = t >> 7;
        const float xsq = xsq_s[row];
        int n = cnt_s[row];
        if (n > CAP) n = CAP;
        for (int ci = half; ci < n; ci += 2)
            rescore_one(Xs, row, cand_s[row * CAP + ci], xsq, esq_s, best_s);
    }
    __syncthreads();

    // overflow rows (cnt > CAP): full rescore by entire CTA (rare)
    for (int r = 0; r < MTILE; ++r) {
        if (cnt_s[r] > CAP) {
            float xsq = xsq_s[r];
            for (int code = t; code < KCODES; code += THREADS)
                rescore_one(Xs, r, code, xsq, esq_s, best_s);
        }
    }
    __syncthreads();

    // publish indices
    if (t < MTILE) {
        int bi = (int)(unsigned)(best_s[t] & 0xFFFFFFFFull);
        idx_out[rowBase + t] = (float)bi;
    }
    __syncthreads();

    // gather winner (coalesced fp32 code-major), write quantized, loss
    float lsum = 0.f;
    const int d = t & 127, half = t >> 7;
    for (int rr = half; rr < MTILE; rr += 2) {
        int bi = (int)(unsigned)(best_s[rr] & 0xFFFFFFFFull);
        float e = __ldg(&g_ET_f32[(size_t)bi * DDIM + d]);
        float x = Xs[rr * XSTRIDE + d];
        q_out[(size_t)(rowBase + rr) * DDIM + d] = e;
        float df = e - x;
        lsum = fmaf(df, df, lsum);
    }
#pragma unroll
    for (int o = 16; o > 0; o >>= 1) lsum += __shfl_xor_sync(0xffffffffu, lsum, o);
    __syncthreads();
    float* rbuf = esq_s;   // esq no longer needed
    if ((t & 31) == 0) rbuf[t >> 5] = lsum;
    __syncthreads();
    if (t == 0) {
        double s = 0.0;
        for (int ww = 0; ww < THREADS / 32; ++ww) s += (double)rbuf[ww];
        atomicAdd(&g_loss_acc, s);
    }
}

// ---- finalize ---------------------------------------------------------------
__global__ void vq_final_kernel(float* loss_out, int numel) {
    loss_out[0] = (float)(0.25 * g_loss_acc / (double)numel);
}

// ----------------------------------------------------------------------------
extern "C" void kernel_launch(void* const* d_in, const int* in_sizes, int n_in,
                              void* d_out, int out_size)
{
    const float* X = (const float*)d_in[0];
    const float* E = (const float*)d_in[1];
    const int N = in_sizes[0] / DDIM;     // 262144

    float* out    = (float*)d_out;
    float* q      = out;
    float* loss_p = out + (size_t)N * DDIM;
    float* idx_p  = out + (size_t)N * DDIM + 1;

    static bool attr_set = false;
    if (!attr_set) {
        cudaFuncSetAttribute(vq_main_kernel,
                             cudaFuncAttributeMaxDynamicSharedMemorySize, SM_TOTAL);
        attr_set = true;
    }

    vq_prep_kernel<<<4, 256>>>(E);
    vq_main_kernel<<<N / MTILE, THREADS, SM_TOTAL>>>(X, q, idx_p);
    vq_final_kernel<<<1, 1>>>(loss_p, N * DDIM);
}

// round 7
// speedup vs baseline: 1.3429x; 1.3429x over previous
#include <cuda_runtime.h>
#include <cuda_bf16.h>
#include <cstdint>

// ----------------------------------------------------------------------------
// VQ: bf16 screening GEMM (tensor cores) + per-row filtered exact rescore.
// inputs : d_in[0] = X [N=262144, D=128] fp32 ; d_in[1] = E [128, 1024] fp32
// outputs: d_out = [ quantized (N*D) | loss (1) | indices-as-float (N) ]
// (resubmission: rounds 5/6 never ran due to container-broker failures)
// ----------------------------------------------------------------------------

#define KCODES  1024
#define DDIM    128
#define MTILE   128
#define NCHUNK  128
#define NCHUNKS 8
#define THREADS 256
#define SLOTS   16              // private slots per thread
#define ROWSLOT 64              // 4 quads * 16

#define XSTRIDE 132             // fp32 X tile row stride (floats)
#define BSTRIDE 272             // E chunk row stride bytes (128 bf16 + 8 pad)

// SMEM layout (bytes)
#define SM_X     0                                  // 67584
#define SM_B     67584                              // 2*128*272 = 69632
#define SM_ESQ   137216                             // 4096
#define SM_XSQ   141312                             // 512
#define SM_BND   141824                             // 512  (2*B per row)
#define SM_CNT4  142336                             // 128*4 ints = 2048
#define SM_OVF   144384                             // 128 ints = 512
#define SM_BEST  144896                             // 128 u64 = 1024
#define SM_RMIN  145920                             // 128 f = 512
#define SM_CAND  146432                             // 128*64*4 = 32768
#define SM_TOTAL 179200

#define BBUF    (MTILE * BSTRIDE)                   // 34816 per buffer

// scratch globals (no cudaMalloc allowed)
__device__ double g_loss_acc;
__device__ __align__(16) float         g_esq[KCODES];
__device__ __align__(16) __nv_bfloat16 g_ET_hh[KCODES * DDIM];   // [k][d] bf16
__device__ __align__(16) float         g_ET_f32[KCODES * DDIM];  // [k][d] fp32

// ---- helpers ----------------------------------------------------------------
__device__ __forceinline__ uint32_t smem_u32(const void* p) {
    uint32_t a;
    asm("{ .reg .u64 t; cvta.to.shared.u64 t, %1; cvt.u32.u64 %0, t; }"
        : "=r"(a) : "l"(p));
    return a;
}
__device__ __forceinline__ void cp_async16(uint32_t dst, const void* src) {
    asm volatile("cp.async.cg.shared.global [%0], [%1], 16;"
                 :: "r"(dst), "l"(src) : "memory");
}
__device__ __forceinline__ void cp_commit() {
    asm volatile("cp.async.commit_group;" ::: "memory");
}
template <int N> __device__ __forceinline__ void cp_wait() {
    asm volatile("cp.async.wait_group %0;" :: "n"(N) : "memory");
}
__device__ __forceinline__ void mma16816(float* d, uint32_t a0, uint32_t a1,
                                         uint32_t a2, uint32_t a3,
                                         uint32_t b0, uint32_t b1) {
    asm volatile(
        "mma.sync.aligned.m16n8k16.row.col.f32.bf16.bf16.f32 "
        "{%0,%1,%2,%3}, {%4,%5,%6,%7}, {%8,%9}, {%0,%1,%2,%3};"
        : "+f"(d[0]), "+f"(d[1]), "+f"(d[2]), "+f"(d[3])
        : "r"(a0), "r"(a1), "r"(a2), "r"(a3), "r"(b0), "r"(b1));
}
__device__ __forceinline__ uint32_t pack_bf2(float x, float y) {
    __nv_bfloat162 v = __halves2bfloat162(__float2bfloat16(x), __float2bfloat16(y));
    return *(uint32_t*)&v;
}
// pack screened dist (+16 bias, positive) into top 22 bits, code in low 10
__device__ __forceinline__ uint32_t pack_cand(float scr, int code) {
    return (__float_as_uint(scr + 16.f) & 0xFFFFFC00u) | (uint32_t)code;
}

// ---- prep: esq, E transpose (bf16 + fp32), zero loss ------------------------
__global__ void vq_prep_kernel(const float* __restrict__ E) {
    int k = blockIdx.x * blockDim.x + threadIdx.x;
    if (k == 0) g_loss_acc = 0.0;
    if (k >= KCODES) return;
    float s = 0.f;
#pragma unroll 8
    for (int d = 0; d < DDIM; ++d) {
        float e = E[(size_t)d * KCODES + k];
        s = fmaf(e, e, s);
        g_ET_hh[k * DDIM + d]  = __float2bfloat16(e);
        g_ET_f32[k * DDIM + d] = e;
    }
    g_esq[k] = s;
}

// ---- issue cp.async for one E chunk into buffer buf -------------------------
__device__ __forceinline__ void issue_B(char* smem, int buf, int c0, int t) {
    uint32_t base = smem_u32(smem + SM_B) + buf * BBUF;
#pragma unroll
    for (int j = 0; j < 8; ++j) {
        int idx = t + j * THREADS;
        int r   = idx >> 4;
        int seg = idx & 15;
        cp_async16(base + r * BSTRIDE + seg * 16,
                   g_ET_hh + (size_t)(c0 + r) * DDIM + seg * 8);
    }
    cp_commit();
}

// ---- exact fp32 rescore of one (row, code); reference rounding --------------
__device__ __forceinline__ void rescore_one(const float* Xs, int row, int code,
                                            float xsq, const float* esq_s,
                                            unsigned long long* best) {
    const float4* xr = (const float4*)&Xs[row * XSTRIDE];
    const float4* er = (const float4*)&g_ET_f32[(size_t)code * DDIM];
    float dot = 0.f;
#pragma unroll 8
    for (int i = 0; i < 32; ++i) {
        float4 xv = xr[i];
        float4 ev = __ldg(&er[i]);
        dot = fmaf(xv.x, ev.x, dot);
        dot = fmaf(xv.y, ev.y, dot);
        dot = fmaf(xv.z, ev.z, dot);
        dot = fmaf(xv.w, ev.w, dot);
    }
    float m  = __fmul_rn(2.f, dot);
    float tt = __fadd_rn(xsq, -m);
    float dd = __fadd_rn(tt, esq_s[code]);
    unsigned long long packed =
        ((unsigned long long)__float_as_uint(dd) << 32) | (unsigned)code;
    atomicMin(&best[row], packed);
}

// ---- main fused kernel ------------------------------------------------------
__global__ __launch_bounds__(THREADS, 1) void vq_main_kernel(
    const float* __restrict__ X, float* __restrict__ q_out, float* __restrict__ idx_out)
{
    extern __shared__ char smem[];
    float* Xs     = (float*)(smem + SM_X);
    float* esq_s  = (float*)(smem + SM_ESQ);
    float* xsq_s  = (float*)(smem + SM_XSQ);
    float* bnd_s  = (float*)(smem + SM_BND);
    int*   cnt4_s = (int*)(smem + SM_CNT4);
    int*   ovf_s  = (int*)(smem + SM_OVF);
    unsigned long long* best_s = (unsigned long long*)(smem + SM_BEST);
    float* rmin_s = (float*)(smem + SM_RMIN);
    uint32_t* cand_s = (uint32_t*)(smem + SM_CAND);

    const int t    = threadIdx.x;
    const int w    = t >> 5;
    const int lane = t & 31;
    const int g    = lane >> 2;          // row within 8-group
    const int qd   = lane & 3;           // quad slot id
    const int q    = qd << 1;            // even col offset
    const int rowBase = blockIdx.x * MTILE;

    issue_B(smem, 0, 0, t);

    for (int i = t; i < KCODES; i += THREADS) esq_s[i] = g_esq[i];
    if (t < MTILE) { ovf_s[t] = 0; best_s[t] = 0xFFFFFFFFFFFFFFFFull; }

    const float4* X4 = (const float4*)(X + (size_t)rowBase * DDIM);
#pragma unroll
    for (int i = 0; i < 16; ++i) {
        int idx = t + i * THREADS;
        int row = idx >> 5;
        int c4  = idx & 31;
        *(float4*)&Xs[row * XSTRIDE + c4 * 4] = X4[idx];
    }
    __syncthreads();

    // per-row ||x||^2 (sequential fmaf) and window 2*B
    if (t < MTILE) {
        float s = 0.f, s1 = 0.f;
#pragma unroll 8
        for (int d = 0; d < DDIM; ++d) {
            float x = Xs[t * XSTRIDE + d];
            s  = fmaf(x, x, s);
            s1 += fabsf(x);
        }
        xsq_s[t] = s;
        bnd_s[t] = 2.f * (1.202e-3f * s1 + 0.004f);
    }

    // A fragments (bf16 of x), reused across chunks
    const int r0 = 16 * w + g;
    const int r1 = r0 + 8;
    uint32_t a[8][4];
#pragma unroll
    for (int ks = 0; ks < 8; ++ks) {
        int k0 = ks * 16;
        float2 f0 = *(const float2*)&Xs[r0 * XSTRIDE + k0 + q];
        float2 f1 = *(const float2*)&Xs[r1 * XSTRIDE + k0 + q];
        float2 f2 = *(const float2*)&Xs[r0 * XSTRIDE + k0 + q + 8];
        float2 f3 = *(const float2*)&Xs[r1 * XSTRIDE + k0 + q + 8];
        a[ks][0] = pack_bf2(f0.x, f0.y);
        a[ks][1] = pack_bf2(f1.x, f1.y);
        a[ks][2] = pack_bf2(f2.x, f2.y);
        a[ks][3] = pack_bf2(f3.x, f3.y);
    }
    __syncthreads();
    const float twoBA = bnd_s[r0], twoBB = bnd_s[r1];

    uint32_t* slotA = &cand_s[r0 * ROWSLOT + qd * SLOTS];
    uint32_t* slotB = &cand_s[r1 * ROWSLOT + qd * SLOTS];
    int cntA = 0, cntB = 0;
    float rmA = 3.402823466e38f, rmB = 3.402823466e38f;

    // ---- screening loop (two acc halves to limit register pressure) --------
    for (int ch = 0; ch < NCHUNKS; ++ch) {
        const int buf = ch & 1;
        if (ch + 1 < NCHUNKS) {
            issue_B(smem, (ch + 1) & 1, (ch + 1) * NCHUNK, t);
            cp_wait<1>();
        } else {
            cp_wait<0>();
        }
        __syncthreads();

        const char* Bh = smem + SM_B + buf * BBUF;
        const int cbase = ch * NCHUNK;

#pragma unroll
        for (int hlf = 0; hlf < 2; ++hlf) {
            float acc[8][4];
#pragma unroll
            for (int nt = 0; nt < 8; ++nt) {
                acc[nt][0] = 0.f; acc[nt][1] = 0.f; acc[nt][2] = 0.f; acc[nt][3] = 0.f;
            }
#pragma unroll
            for (int ks = 0; ks < 8; ++ks) {
                const uint32_t a0 = a[ks][0], a1 = a[ks][1], a2 = a[ks][2], a3 = a[ks][3];
                const int koff0 = (ks * 16 + q) * 2;
                const int koff1 = (ks * 16 + q + 8) * 2;
#pragma unroll
                for (int nt = 0; nt < 8; ++nt) {
                    const char* rowp = Bh + ((hlf * 8 + nt) * 8 + g) * BSTRIDE;
                    uint32_t b0 = *(const uint32_t*)(rowp + koff0);
                    uint32_t b1 = *(const uint32_t*)(rowp + koff1);
                    mma16816(acc[nt], a0, a1, a2, a3, b0, b1);
                }
            }
            // fold: scr = esq - 2*dot ; private-slot push, no atomics
#pragma unroll
            for (int nt = 0; nt < 8; ++nt) {
                int cA = cbase + (hlf * 8 + nt) * 8 + q;
                float2 e2 = *(const float2*)&esq_s[cA];
                float tv;
                tv = fmaf(-2.f, acc[nt][0], e2.x);
                if (tv < rmA + twoBA) {
                    if (cntA < SLOTS) slotA[cntA] = pack_cand(tv, cA);
                    ++cntA;
                    rmA = fminf(rmA, tv);
                }
                tv = fmaf(-2.f, acc[nt][1], e2.y);
                if (tv < rmA + twoBA) {
                    if (cntA < SLOTS) slotA[cntA] = pack_cand(tv, cA + 1);
                    ++cntA;
                    rmA = fminf(rmA, tv);
                }
                tv = fmaf(-2.f, acc[nt][2], e2.x);
                if (tv < rmB + twoBB) {
                    if (cntB < SLOTS) slotB[cntB] = pack_cand(tv, cA);
                    ++cntB;
                    rmB = fminf(rmB, tv);
                }
                tv = fmaf(-2.f, acc[nt][3], e2.y);
                if (tv < rmB + twoBB) {
                    if (cntB < SLOTS) slotB[cntB] = pack_cand(tv, cA + 1);
                    ++cntB;
                    rmB = fminf(rmB, tv);
                }
            }
        }
        __syncthreads();   // buffer reuse
    }

    // ---- per-row screened min (quad reduce) + publish counts ----------------
#pragma unroll
    for (int off = 1; off <= 2; off <<= 1) {
        rmA = fminf(rmA, __shfl_xor_sync(0xffffffffu, rmA, off));
        rmB = fminf(rmB, __shfl_xor_sync(0xffffffffu, rmB, off));
    }
    cnt4_s[r0 * 4 + qd] = (cntA < SLOTS) ? cntA : SLOTS;
    cnt4_s[r1 * 4 + qd] = (cntB < SLOTS) ? cntB : SLOTS;
    if (cntA > SLOTS) ovf_s[r0] = 1;
    if (cntB > SLOTS) ovf_s[r1] = 1;
    if (qd == 0) { rmin_s[r0] = rmA; rmin_s[r1] = rmB; }
    __syncthreads();

    // ---- filter candidates vs row threshold; exact rescore survivors --------
    {
        const int row  = t & 127;
        const int half = t >> 7;
        if (!ovf_s[row]) {
            const float xsq = xsq_s[row];
            // packed compare value: scr+16, widened for 10-bit mantissa drop
            const float thr = rmin_s[row] + bnd_s[row] + 16.f + 0.01f;
#pragma unroll
            for (int qq = half * 2; qq < half * 2 + 2; ++qq) {
                int n = cnt4_s[row * 4 + qq];
                const uint32_t* sl = &cand_s[row * ROWSLOT + qq * SLOTS];
                for (int ci = 0; ci < n; ++ci) {
                    uint32_t pk = sl[ci];
                    float scr = __uint_as_float(pk & 0xFFFFFC00u);
                    if (scr <= thr)
                        rescore_one(Xs, row, (int)(pk & 1023u), xsq, esq_s, best_s);
                }
            }
        }
    }
    // overflow rows (rare): full exact rescore by whole CTA
    for (int r = 0; r < MTILE; ++r) {
        if (ovf_s[r]) {
            float xsq = xsq_s[r];
            for (int code = t; code < KCODES; code += THREADS)
                rescore_one(Xs, r, code, xsq, esq_s, best_s);
        }
    }
    __syncthreads();

    if (t < MTILE) {
        int bi = (int)(unsigned)(best_s[t] & 0xFFFFFFFFull);
        idx_out[rowBase + t] = (float)bi;
    }
    __syncthreads();

    // gather winner (coalesced fp32 code-major), write quantized, loss
    float lsum = 0.f;
    const int d = t & 127, half = t >> 7;
    for (int rr = half; rr < MTILE; rr += 2) {
        int bi = (int)(unsigned)(best_s[rr] & 0xFFFFFFFFull);
        float e = __ldg(&g_ET_f32[(size_t)bi * DDIM + d]);
        float x = Xs[rr * XSTRIDE + d];
        q_out[(size_t)(rowBase + rr) * DDIM + d] = e;
        float df = e - x;
        lsum = fmaf(df, df, lsum);
    }
#pragma unroll
    for (int o = 16; o > 0; o >>= 1) lsum += __shfl_xor_sync(0xffffffffu, lsum, o);
    __syncthreads();
    float* rbuf = esq_s;
    if ((t & 31) == 0) rbuf[t >> 5] = lsum;
    __syncthreads();
    if (t == 0) {
        double s = 0.0;
        for (int ww = 0; ww < THREADS / 32; ++ww) s += (double)rbuf[ww];
        atomicAdd(&g_loss_acc, s);
    }
}

// ---- finalize ---------------------------------------------------------------
__global__ void vq_final_kernel(float* loss_out, int numel) {
    loss_out[0] = (float)(0.25 * g_loss_acc / (double)numel);
}

// ----------------------------------------------------------------------------
extern "C" void kernel_launch(void* const* d_in, const int* in_sizes, int n_in,
                              void* d_out, int out_size)
{
    const float* X = (const float*)d_in[0];
    const float* E = (const float*)d_in[1];
    const int N = in_sizes[0] / DDIM;     // 262144

    float* out    = (float*)d_out;
    float* q      = out;
    float* loss_p = out + (size_t)N * DDIM;
    float* idx_p  = out + (size_t)N * DDIM + 1;

    static bool attr_set = false;
    if (!attr_set) {
        cudaFuncSetAttribute(vq_main_kernel,
                             cudaFuncAttributeMaxDynamicSharedMemorySize, SM_TOTAL);
        attr_set = true;
    }

    vq_prep_kernel<<<4, 256>>>(E);
    vq_main_kernel<<<N / MTILE, THREADS, SM_TOTAL>>>(X, q, idx_p);
    vq_final_kernel<<<1, 1>>>(loss_p, N * DDIM);
}

// round 10
// speedup vs baseline: 2.0394x; 1.5186x over previous
#include <cuda_runtime.h>
#include <cuda_bf16.h>
#include <cstdint>

// ----------------------------------------------------------------------------
// VQ: bf16 screening GEMM (tensor cores) + per-row filtered exact rescore.
// Round 10 (= branchless-push design, third submission; broker flaked twice):
// branchless candidate push (SEL + unconditional STS), SLOTS=24,
// conflict-free slot stride 97.
// inputs : d_in[0] = X [N=262144, D=128] fp32 ; d_in[1] = E [128, 1024] fp32
// outputs: d_out = [ quantized (N*D) | loss (1) | indices-as-float (N) ]
// ----------------------------------------------------------------------------

#define KCODES  1024
#define DDIM    128
#define MTILE   128
#define NCHUNK  128
#define NCHUNKS 8
#define THREADS 256
#define SLOTS   24              // private slots per thread
#define ROWSLOT 97              // words per row (4*24 padded to odd stride)

#define XSTRIDE 132             // fp32 X tile row stride (floats)
#define BSTRIDE 272             // E chunk row stride bytes (128 bf16 + 8 pad)

// SMEM layout (bytes)
#define SM_X     0                                  // 67584
#define SM_B     67584                              // 2*128*272 = 69632
#define SM_ESQ   137216                             // 4096
#define SM_XSQ   141312                             // 512
#define SM_BND   141824                             // 512  (2*B per row)
#define SM_CNT4  142336                             // 128*4 ints = 2048
#define SM_OVF   144384                             // 128 ints = 512
#define SM_BEST  144896                             // 128 u64 = 1024
#define SM_RMIN  145920                             // 128 f = 512
#define SM_CAND  146432                             // 128*97*4 = 49664
#define SM_TOTAL 196096

#define BBUF    (MTILE * BSTRIDE)                   // 34816 per buffer

// scratch globals (no cudaMalloc allowed)
__device__ double g_loss_acc;
__device__ __align__(16) float         g_esq[KCODES];
__device__ __align__(16) __nv_bfloat16 g_ET_hh[KCODES * DDIM];   // [k][d] bf16
__device__ __align__(16) float         g_ET_f32[KCODES * DDIM];  // [k][d] fp32

// ---- helpers ----------------------------------------------------------------
__device__ __forceinline__ uint32_t smem_u32(const void* p) {
    uint32_t a;
    asm("{ .reg .u64 t; cvta.to.shared.u64 t, %1; cvt.u32.u64 %0, t; }"
        : "=r"(a) : "l"(p));
    return a;
}
__device__ __forceinline__ void cp_async16(uint32_t dst, const void* src) {
    asm volatile("cp.async.cg.shared.global [%0], [%1], 16;"
                 :: "r"(dst), "l"(src) : "memory");
}
__device__ __forceinline__ void cp_commit() {
    asm volatile("cp.async.commit_group;" ::: "memory");
}
template <int N> __device__ __forceinline__ void cp_wait() {
    asm volatile("cp.async.wait_group %0;" :: "n"(N) : "memory");
}
__device__ __forceinline__ void mma16816(float* d, uint32_t a0, uint32_t a1,
                                         uint32_t a2, uint32_t a3,
                                         uint32_t b0, uint32_t b1) {
    asm volatile(
        "mma.sync.aligned.m16n8k16.row.col.f32.bf16.bf16.f32 "
        "{%0,%1,%2,%3}, {%4,%5,%6,%7}, {%8,%9}, {%0,%1,%2,%3};"
        : "+f"(d[0]), "+f"(d[1]), "+f"(d[2]), "+f"(d[3])
        : "r"(a0), "r"(a1), "r"(a2), "r"(a3), "r"(b0), "r"(b1));
}
__device__ __forceinline__ uint32_t pack_bf2(float x, float y) {
    __nv_bfloat162 v = __halves2bfloat162(__float2bfloat16(x), __float2bfloat16(y));
    return *(uint32_t*)&v;
}
// pack screened dist (+16 bias, positive) into top 22 bits, code in low 10
__device__ __forceinline__ uint32_t pack_cand(float scr, int code) {
    return (__float_as_uint(scr + 16.f) & 0xFFFFFC00u) | (uint32_t)code;
}
// branchless push: always stores (sentinel when !c), counter advances only on c
__device__ __forceinline__ void push_cand(uint32_t* slot, int& cnt,
                                          bool c, float tv, int code,
                                          float& rm) {
    uint32_t val = c ? pack_cand(tv, code) : 0u;
    int idx = (cnt < SLOTS - 1) ? cnt : (SLOTS - 1);
    slot[idx] = val;
    cnt += (int)c;
    rm = fminf(rm, tv);
}

// ---- prep: esq, E transpose (bf16 + fp32), zero loss ------------------------
__global__ void vq_prep_kernel(const float* __restrict__ E) {
    int k = blockIdx.x * blockDim.x + threadIdx.x;
    if (k == 0) g_loss_acc = 0.0;
    if (k >= KCODES) return;
    float s = 0.f;
#pragma unroll 8
    for (int d = 0; d < DDIM; ++d) {
        float e = E[(size_t)d * KCODES + k];
        s = fmaf(e, e, s);
        g_ET_hh[k * DDIM + d]  = __float2bfloat16(e);
        g_ET_f32[k * DDIM + d] = e;
    }
    g_esq[k] = s;
}

// ---- issue cp.async for one E chunk into buffer buf -------------------------
__device__ __forceinline__ void issue_B(char* smem, int buf, int c0, int t) {
    uint32_t base = smem_u32(smem + SM_B) + buf * BBUF;
#pragma unroll
    for (int j = 0; j < 8; ++j) {
        int idx = t + j * THREADS;
        int r   = idx >> 4;
        int seg = idx & 15;
        cp_async16(base + r * BSTRIDE + seg * 16,
                   g_ET_hh + (size_t)(c0 + r) * DDIM + seg * 8);
    }
    cp_commit();
}

// ---- exact fp32 rescore of one (row, code); reference rounding --------------
__device__ __forceinline__ void rescore_one(const float* Xs, int row, int code,
                                            float xsq, const float* esq_s,
                                            unsigned long long* best) {
    const float4* xr = (const float4*)&Xs[row * XSTRIDE];
    const float4* er = (const float4*)&g_ET_f32[(size_t)code * DDIM];
    float dot = 0.f;
#pragma unroll 8
    for (int i = 0; i < 32; ++i) {
        float4 xv = xr[i];
        float4 ev = __ldg(&er[i]);
        dot = fmaf(xv.x, ev.x, dot);
        dot = fmaf(xv.y, ev.y, dot);
        dot = fmaf(xv.z, ev.z, dot);
        dot = fmaf(xv.w, ev.w, dot);
    }
    float m  = __fmul_rn(2.f, dot);
    float tt = __fadd_rn(xsq, -m);
    float dd = __fadd_rn(tt, esq_s[code]);
    unsigned long long packed =
        ((unsigned long long)__float_as_uint(dd) << 32) | (unsigned)code;
    atomicMin(&best[row], packed);
}

// ---- main fused kernel ------------------------------------------------------
__global__ __launch_bounds__(THREADS, 1) void vq_main_kernel(
    const float* __restrict__ X, float* __restrict__ q_out, float* __restrict__ idx_out)
{
    extern __shared__ char smem[];
    float* Xs     = (float*)(smem + SM_X);
    float* esq_s  = (float*)(smem + SM_ESQ);
    float* xsq_s  = (float*)(smem + SM_XSQ);
    float* bnd_s  = (float*)(smem + SM_BND);
    int*   cnt4_s = (int*)(smem + SM_CNT4);
    int*   ovf_s  = (int*)(smem + SM_OVF);
    unsigned long long* best_s = (unsigned long long*)(smem + SM_BEST);
    float* rmin_s = (float*)(smem + SM_RMIN);
    uint32_t* cand_s = (uint32_t*)(smem + SM_CAND);

    const int t    = threadIdx.x;
    const int w    = t >> 5;
    const int lane = t & 31;
    const int g    = lane >> 2;          // row within 8-group
    const int qd   = lane & 3;           // quad slot id
    const int q    = qd << 1;            // even col offset
    const int rowBase = blockIdx.x * MTILE;

    issue_B(smem, 0, 0, t);

    for (int i = t; i < KCODES; i += THREADS) esq_s[i] = g_esq[i];
    if (t < MTILE) { ovf_s[t] = 0; best_s[t] = 0xFFFFFFFFFFFFFFFFull; }

    const float4* X4 = (const float4*)(X + (size_t)rowBase * DDIM);
#pragma unroll
    for (int i = 0; i < 16; ++i) {
        int idx = t + i * THREADS;
        int row = idx >> 5;
        int c4  = idx & 31;
        *(float4*)&Xs[row * XSTRIDE + c4 * 4] = X4[idx];
    }
    __syncthreads();

    // per-row ||x||^2 (sequential fmaf) and window 2*B
    if (t < MTILE) {
        float s = 0.f, s1 = 0.f;
#pragma unroll 8
        for (int d = 0; d < DDIM; ++d) {
            float x = Xs[t * XSTRIDE + d];
            s  = fmaf(x, x, s);
            s1 += fabsf(x);
        }
        xsq_s[t] = s;
        bnd_s[t] = 2.f * (1.202e-3f * s1 + 0.004f);
    }

    // A fragments (bf16 of x), reused across chunks
    const int r0 = 16 * w + g;
    const int r1 = r0 + 8;
    uint32_t a[8][4];
#pragma unroll
    for (int ks = 0; ks < 8; ++ks) {
        int k0 = ks * 16;
        float2 f0 = *(const float2*)&Xs[r0 * XSTRIDE + k0 + q];
        float2 f1 = *(const float2*)&Xs[r1 * XSTRIDE + k0 + q];
        float2 f2 = *(const float2*)&Xs[r0 * XSTRIDE + k0 + q + 8];
        float2 f3 = *(const float2*)&Xs[r1 * XSTRIDE + k0 + q + 8];
        a[ks][0] = pack_bf2(f0.x, f0.y);
        a[ks][1] = pack_bf2(f1.x, f1.y);
        a[ks][2] = pack_bf2(f2.x, f2.y);
        a[ks][3] = pack_bf2(f3.x, f3.y);
    }
    __syncthreads();
    const float twoBA = bnd_s[r0], twoBB = bnd_s[r1];

    uint32_t* slotA = &cand_s[r0 * ROWSLOT + qd * SLOTS];
    uint32_t* slotB = &cand_s[r1 * ROWSLOT + qd * SLOTS];
    int cntA = 0, cntB = 0;
    float rmA = 3.402823466e38f, rmB = 3.402823466e38f;

    // ---- screening loop (two acc halves to limit register pressure) --------
    for (int ch = 0; ch < NCHUNKS; ++ch) {
        const int buf = ch & 1;
        if (ch + 1 < NCHUNKS) {
            issue_B(smem, (ch + 1) & 1, (ch + 1) * NCHUNK, t);
            cp_wait<1>();
        } else {
            cp_wait<0>();
        }
        __syncthreads();

        const char* Bh = smem + SM_B + buf * BBUF;
        const int cbase = ch * NCHUNK;

#pragma unroll
        for (int hlf = 0; hlf < 2; ++hlf) {
            float acc[8][4];
#pragma unroll
            for (int nt = 0; nt < 8; ++nt) {
                acc[nt][0] = 0.f; acc[nt][1] = 0.f; acc[nt][2] = 0.f; acc[nt][3] = 0.f;
            }
#pragma unroll
            for (int ks = 0; ks < 8; ++ks) {
                const uint32_t a0 = a[ks][0], a1 = a[ks][1], a2 = a[ks][2], a3 = a[ks][3];
                const int koff0 = (ks * 16 + q) * 2;
                const int koff1 = (ks * 16 + q + 8) * 2;
#pragma unroll
                for (int nt = 0; nt < 8; ++nt) {
                    const char* rowp = Bh + ((hlf * 8 + nt) * 8 + g) * BSTRIDE;
                    uint32_t b0 = *(const uint32_t*)(rowp + koff0);
                    uint32_t b1 = *(const uint32_t*)(rowp + koff1);
                    mma16816(acc[nt], a0, a1, a2, a3, b0, b1);
                }
            }
            // fold: scr = esq - 2*dot ; fully branchless push
#pragma unroll
            for (int nt = 0; nt < 8; ++nt) {
                int cA = cbase + (hlf * 8 + nt) * 8 + q;
                float2 e2 = *(const float2*)&esq_s[cA];
                float tv;
                tv = fmaf(-2.f, acc[nt][0], e2.x);
                push_cand(slotA, cntA, tv < rmA + twoBA, tv, cA, rmA);
                tv = fmaf(-2.f, acc[nt][1], e2.y);
                push_cand(slotA, cntA, tv < rmA + twoBA, tv, cA + 1, rmA);
                tv = fmaf(-2.f, acc[nt][2], e2.x);
                push_cand(slotB, cntB, tv < rmB + twoBB, tv, cA, rmB);
                tv = fmaf(-2.f, acc[nt][3], e2.y);
                push_cand(slotB, cntB, tv < rmB + twoBB, tv, cA + 1, rmB);
            }
        }
        __syncthreads();   // buffer reuse
    }

    // ---- per-row screened min (quad reduce) + publish counts ----------------
#pragma unroll
    for (int off = 1; off <= 2; off <<= 1) {
        rmA = fminf(rmA, __shfl_xor_sync(0xffffffffu, rmA, off));
        rmB = fminf(rmB, __shfl_xor_sync(0xffffffffu, rmB, off));
    }
    cnt4_s[r0 * 4 + qd] = (cntA < SLOTS) ? cntA : SLOTS;
    cnt4_s[r1 * 4 + qd] = (cntB < SLOTS) ? cntB : SLOTS;
    if (cntA >= SLOTS) ovf_s[r0] = 1;     // slot (SLOTS-1) may be corrupted
    if (cntB >= SLOTS) ovf_s[r1] = 1;
    if (qd == 0) { rmin_s[r0] = rmA; rmin_s[r1] = rmB; }
    __syncthreads();

    // ---- filter candidates vs row threshold; exact rescore survivors --------
    {
        const int row  = t & 127;
        const int half = t >> 7;
        if (!ovf_s[row]) {
            const float xsq = xsq_s[row];
            // packed compare value: scr+16, widened for 10-bit mantissa drop
            const float thr = rmin_s[row] + bnd_s[row] + 16.f + 0.01f;
#pragma unroll
            for (int qq = half * 2; qq < half * 2 + 2; ++qq) {
                int n = cnt4_s[row * 4 + qq];
                const uint32_t* sl = &cand_s[row * ROWSLOT + qq * SLOTS];
                for (int ci = 0; ci < n; ++ci) {
                    uint32_t pk = sl[ci];
                    float scr = __uint_as_float(pk & 0xFFFFFC00u);
                    if (scr <= thr)
                        rescore_one(Xs, row, (int)(pk & 1023u), xsq, esq_s, best_s);
                }
            }
        }
    }
    // overflow rows (rare): full exact rescore by whole CTA
    for (int r = 0; r < MTILE; ++r) {
        if (ovf_s[r]) {
            float xsq = xsq_s[r];
            for (int code = t; code < KCODES; code += THREADS)
                rescore_one(Xs, r, code, xsq, esq_s, best_s);
        }
    }
    __syncthreads();

    if (t < MTILE) {
        int bi = (int)(unsigned)(best_s[t] & 0xFFFFFFFFull);
        idx_out[rowBase + t] = (float)bi;
    }
    __syncthreads();

    // gather winner (coalesced fp32 code-major), write quantized, loss
    float lsum = 0.f;
    const int d = t & 127, half = t >> 7;
    for (int rr = half; rr < MTILE; rr += 2) {
        int bi = (int)(unsigned)(best_s[rr] & 0xFFFFFFFFull);
        float e = __ldg(&g_ET_f32[(size_t)bi * DDIM + d]);
        float x = Xs[rr * XSTRIDE + d];
        q_out[(size_t)(rowBase + rr) * DDIM + d] = e;
        float df = e - x;
        lsum = fmaf(df, df, lsum);
    }
#pragma unroll
    for (int o = 16; o > 0; o >>= 1) lsum += __shfl_xor_sync(0xffffffffu, lsum, o);
    __syncthreads();
    float* rbuf = esq_s;
    if ((t & 31) == 0) rbuf[t >> 5] = lsum;
    __syncthreads();
    if (t == 0) {
        double s = 0.0;
        for (int ww = 0; ww < THREADS / 32; ++ww) s += (double)rbuf[ww];
        atomicAdd(&g_loss_acc, s);
    }
}

// ---- finalize ---------------------------------------------------------------
__global__ void vq_final_kernel(float* loss_out, int numel) {
    loss_out[0] = (float)(0.25 * g_loss_acc / (double)numel);
}

// ----------------------------------------------------------------------------
extern "C" void kernel_launch(void* const* d_in, const int* in_sizes, int n_in,
                              void* d_out, int out_size)
{
    const float* X = (const float*)d_in[0];
    const float* E = (const float*)d_in[1];
    const int N = in_sizes[0] / DDIM;     // 262144

    float* out    = (float*)d_out;
    float* q      = out;
    float* loss_p = out + (size_t)N * DDIM;
    float* idx_p  = out + (size_t)N * DDIM + 1;

    static bool attr_set = false;
    if (!attr_set) {
        cudaFuncSetAttribute(vq_main_kernel,
                             cudaFuncAttributeMaxDynamicSharedMemorySize, SM_TOTAL);
        attr_set = true;
    }

    vq_prep_kernel<<<4, 256>>>(E);
    vq_main_kernel<<<N / MTILE, THREADS, SM_TOTAL>>>(X, q, idx_p);
    vq_final_kernel<<<1, 1>>>(loss_p, N * DDIM);
}

// round 11
// speedup vs baseline: 2.2880x; 1.1219x over previous
#include <cuda_runtime.h>
#include <cuda_bf16.h>
#include <cstdint>

// ----------------------------------------------------------------------------
// VQ: bf16 screening GEMM + per-row filtered exact rescore.
// Round 11: ILP fold — two-pass frozen-threshold push (no serial rm/cond
// chains), permuted-E LDS.64 B fragments, 4-way rescore dot.
// inputs : d_in[0] = X [N=262144, D=128] fp32 ; d_in[1] = E [128, 1024] fp32
// outputs: d_out = [ quantized (N*D) | loss (1) | indices-as-float (N) ]
// ----------------------------------------------------------------------------

#define KCODES  1024
#define DDIM    128
#define MTILE   128
#define NCHUNK  128
#define NCHUNKS 8
#define THREADS 256
#define SLOTS   24
#define ROWSLOT 97

#define XSTRIDE 132             // fp32 X tile row stride (floats)
#define BSTRIDE 288             // E chunk row stride bytes (256B data + 32 pad)

// SMEM layout (bytes)
#define SM_X     0                                  // 67584
#define SM_B     67584                              // 2*128*288 = 73728
#define SM_ESQ   141312                             // 4096
#define SM_XSQ   145408                             // 512
#define SM_BND   145920                             // 512
#define SM_CNT4  146432                             // 2048
#define SM_OVF   148480                             // 512
#define SM_BEST  148992                             // 1024 (8B aligned)
#define SM_RMIN  150016                             // 512
#define SM_CAND  150528                             // 128*97*4 = 49664
#define SM_TOTAL 200192

#define BBUF    (MTILE * BSTRIDE)                   // 36864 per buffer

// scratch globals (no cudaMalloc allowed)
__device__ double g_loss_acc;
__device__ __align__(16) float         g_esq[KCODES];
__device__ __align__(16) __nv_bfloat16 g_ET_hh[KCODES * DDIM];   // [k][perm(d)]
__device__ __align__(16) float         g_ET_f32[KCODES * DDIM];  // [k][d]

// ---- helpers ----------------------------------------------------------------
__device__ __forceinline__ uint32_t smem_u32(const void* p) {
    uint32_t a;
    asm("{ .reg .u64 t; cvta.to.shared.u64 t, %1; cvt.u32.u64 %0, t; }"
        : "=r"(a) : "l"(p));
    return a;
}
__device__ __forceinline__ void cp_async16(uint32_t dst, const void* src) {
    asm volatile("cp.async.cg.shared.global [%0], [%1], 16;"
                 :: "r"(dst), "l"(src) : "memory");
}
__device__ __forceinline__ void cp_commit() {
    asm volatile("cp.async.commit_group;" ::: "memory");
}
template <int N> __device__ __forceinline__ void cp_wait() {
    asm volatile("cp.async.wait_group %0;" :: "n"(N) : "memory");
}
__device__ __forceinline__ void mma16816(float* d, uint32_t a0, uint32_t a1,
                                         uint32_t a2, uint32_t a3,
                                         uint32_t b0, uint32_t b1) {
    asm volatile(
        "mma.sync.aligned.m16n8k16.row.col.f32.bf16.bf16.f32 "
        "{%0,%1,%2,%3}, {%4,%5,%6,%7}, {%8,%9}, {%0,%1,%2,%3};"
        : "+f"(d[0]), "+f"(d[1]), "+f"(d[2]), "+f"(d[3])
        : "r"(a0), "r"(a1), "r"(a2), "r"(a3), "r"(b0), "r"(b1));
}
__device__ __forceinline__ uint32_t pack_bf2(float x, float y) {
    __nv_bfloat162 v = __halves2bfloat162(__float2bfloat16(x), __float2bfloat16(y));
    return *(uint32_t*)&v;
}
// pack screened dist (+16 bias, positive) into top 22 bits, code in low 10
__device__ __forceinline__ uint32_t pack_cand(float scr, int code) {
    return (__float_as_uint(scr + 16.f) & 0xFFFFFC00u) | (uint32_t)code;
}
// branchless push vs FROZEN threshold (thr is a loop-invariant register)
__device__ __forceinline__ void push_cand2(uint32_t* slot, int& cnt,
                                           float tv, float thr, int code) {
    bool c = tv <= thr;
    uint32_t val = c ? pack_cand(tv, code) : 0u;
    int idx = (cnt < SLOTS - 1) ? cnt : (SLOTS - 1);
    slot[idx] = val;
    cnt += (int)c;
}

// d-permutation so a thread's 4 B bytes {q,q+1,q+8,q+9} are contiguous 8B
__device__ __forceinline__ int perm_d(int d) {
    int j = d & 15;
    int p = (j < 8) ? ((j >> 1) * 4 + (j & 1)) : (((j - 8) >> 1) * 4 + 2 + (j & 1));
    return (d & ~15) | p;
}

// ---- prep: esq, E transpose (permuted bf16 + fp32), zero loss ---------------
__global__ void vq_prep_kernel(const float* __restrict__ E) {
    int k = blockIdx.x * blockDim.x + threadIdx.x;
    if (k == 0) g_loss_acc = 0.0;
    if (k >= KCODES) return;
    float s = 0.f;
#pragma unroll 8
    for (int d = 0; d < DDIM; ++d) {
        float e = E[(size_t)d * KCODES + k];
        s = fmaf(e, e, s);
        g_ET_hh[k * DDIM + perm_d(d)] = __float2bfloat16(e);
        g_ET_f32[k * DDIM + d]        = e;
    }
    g_esq[k] = s;
}

// ---- issue cp.async for one E chunk into buffer buf -------------------------
__device__ __forceinline__ void issue_B(char* smem, int buf, int c0, int t) {
    uint32_t base = smem_u32(smem + SM_B) + buf * BBUF;
#pragma unroll
    for (int j = 0; j < 8; ++j) {
        int idx = t + j * THREADS;
        int r   = idx >> 4;
        int seg = idx & 15;
        cp_async16(base + r * BSTRIDE + seg * 16,
                   g_ET_hh + (size_t)(c0 + r) * DDIM + seg * 8);
    }
    cp_commit();
}

// ---- exact fp32 rescore of one (row, code); 4-way dot -----------------------
__device__ __forceinline__ void rescore_one(const float* Xs, int row, int code,
                                            float xsq, const float* esq_s,
                                            unsigned long long* best) {
    const float4* xr = (const float4*)&Xs[row * XSTRIDE];
    const float4* er = (const float4*)&g_ET_f32[(size_t)code * DDIM];
    float s0 = 0.f, s1 = 0.f, s2 = 0.f, s3 = 0.f;
#pragma unroll 8
    for (int i = 0; i < 32; i += 4) {
        float4 xa = xr[i],     ea = __ldg(&er[i]);
        float4 xb = xr[i + 1], eb = __ldg(&er[i + 1]);
        float4 xc = xr[i + 2], ec = __ldg(&er[i + 2]);
        float4 xd = xr[i + 3], ed = __ldg(&er[i + 3]);
        s0 = fmaf(xa.x, ea.x, s0); s0 = fmaf(xa.y, ea.y, s0);
        s0 = fmaf(xa.z, ea.z, s0); s0 = fmaf(xa.w, ea.w, s0);
        s1 = fmaf(xb.x, eb.x, s1); s1 = fmaf(xb.y, eb.y, s1);
        s1 = fmaf(xb.z, eb.z, s1); s1 = fmaf(xb.w, eb.w, s1);
        s2 = fmaf(xc.x, ec.x, s2); s2 = fmaf(xc.y, ec.y, s2);
        s2 = fmaf(xc.z, ec.z, s2); s2 = fmaf(xc.w, ec.w, s2);
        s3 = fmaf(xd.x, ed.x, s3); s3 = fmaf(xd.y, ed.y, s3);
        s3 = fmaf(xd.z, ed.z, s3); s3 = fmaf(xd.w, ed.w, s3);
    }
    float dot = (s0 + s1) + (s2 + s3);
    float m  = __fmul_rn(2.f, dot);
    float tt = __fadd_rn(xsq, -m);
    float dd = __fadd_rn(tt, esq_s[code]);
    unsigned long long packed =
        ((unsigned long long)__float_as_uint(dd) << 32) | (unsigned)code;
    atomicMin(&best[row], packed);
}

// ---- main fused kernel ------------------------------------------------------
__global__ __launch_bounds__(THREADS, 1) void vq_main_kernel(
    const float* __restrict__ X, float* __restrict__ q_out, float* __restrict__ idx_out)
{
    extern __shared__ char smem[];
    float* Xs     = (float*)(smem + SM_X);
    float* esq_s  = (float*)(smem + SM_ESQ);
    float* xsq_s  = (float*)(smem + SM_XSQ);
    float* bnd_s  = (float*)(smem + SM_BND);
    int*   cnt4_s = (int*)(smem + SM_CNT4);
    int*   ovf_s  = (int*)(smem + SM_OVF);
    unsigned long long* best_s = (unsigned long long*)(smem + SM_BEST);
    float* rmin_s = (float*)(smem + SM_RMIN);
    uint32_t* cand_s = (uint32_t*)(smem + SM_CAND);

    const int t    = threadIdx.x;
    const int w    = t >> 5;
    const int lane = t & 31;
    const int g    = lane >> 2;          // row within 8-group
    const int qd   = lane & 3;           // quad slot id
    const int q    = qd << 1;            // even col offset
    const int rowBase = blockIdx.x * MTILE;

    issue_B(smem, 0, 0, t);

    for (int i = t; i < KCODES; i += THREADS) esq_s[i] = g_esq[i];
    if (t < MTILE) { ovf_s[t] = 0; best_s[t] = 0xFFFFFFFFFFFFFFFFull; }

    const float4* X4 = (const float4*)(X + (size_t)rowBase * DDIM);
#pragma unroll
    for (int i = 0; i < 16; ++i) {
        int idx = t + i * THREADS;
        int row = idx >> 5;
        int c4  = idx & 31;
        *(float4*)&Xs[row * XSTRIDE + c4 * 4] = X4[idx];
    }
    __syncthreads();

    // per-row ||x||^2 (sequential fmaf) and window 2*B
    if (t < MTILE) {
        float s = 0.f, s1 = 0.f;
#pragma unroll 8
        for (int d = 0; d < DDIM; ++d) {
            float x = Xs[t * XSTRIDE + d];
            s  = fmaf(x, x, s);
            s1 += fabsf(x);
        }
        xsq_s[t] = s;
        bnd_s[t] = 2.f * (1.202e-3f * s1 + 0.004f);
    }

    // A fragments (bf16 of x), reused across chunks
    const int r0 = 16 * w + g;
    const int r1 = r0 + 8;
    uint32_t a[8][4];
#pragma unroll
    for (int ks = 0; ks < 8; ++ks) {
        int k0 = ks * 16;
        float2 f0 = *(const float2*)&Xs[r0 * XSTRIDE + k0 + q];
        float2 f1 = *(const float2*)&Xs[r1 * XSTRIDE + k0 + q];
        float2 f2 = *(const float2*)&Xs[r0 * XSTRIDE + k0 + q + 8];
        float2 f3 = *(const float2*)&Xs[r1 * XSTRIDE + k0 + q + 8];
        a[ks][0] = pack_bf2(f0.x, f0.y);
        a[ks][1] = pack_bf2(f1.x, f1.y);
        a[ks][2] = pack_bf2(f2.x, f2.y);
        a[ks][3] = pack_bf2(f3.x, f3.y);
    }
    __syncthreads();
    const float twoBA = bnd_s[r0], twoBB = bnd_s[r1];

    uint32_t* slotA = &cand_s[r0 * ROWSLOT + qd * SLOTS];
    uint32_t* slotB = &cand_s[r1 * ROWSLOT + qd * SLOTS];
    int cntA = 0, cntB = 0;
    float rmA = 3.402823466e38f, rmB = 3.402823466e38f;

    // ---- screening loop -----------------------------------------------------
    for (int ch = 0; ch < NCHUNKS; ++ch) {
        const int buf = ch & 1;
        if (ch + 1 < NCHUNKS) {
            issue_B(smem, (ch + 1) & 1, (ch + 1) * NCHUNK, t);
            cp_wait<1>();
        } else {
            cp_wait<0>();
        }
        __syncthreads();

        const char* Bh = smem + SM_B + buf * BBUF;
        const int cbase = ch * NCHUNK;

#pragma unroll
        for (int hlf = 0; hlf < 2; ++hlf) {
            float acc[8][4];
#pragma unroll
            for (int nt = 0; nt < 8; ++nt) {
                acc[nt][0] = 0.f; acc[nt][1] = 0.f; acc[nt][2] = 0.f; acc[nt][3] = 0.f;
            }
#pragma unroll
            for (int ks = 0; ks < 8; ++ks) {
                const uint32_t a0 = a[ks][0], a1 = a[ks][1], a2 = a[ks][2], a3 = a[ks][3];
                const int koff = ks * 32 + qd * 8;     // permuted layout: LDS.64
#pragma unroll
                for (int nt = 0; nt < 8; ++nt) {
                    const char* rowp = Bh + ((hlf * 8 + nt) * 8 + g) * BSTRIDE;
                    uint2 b = *(const uint2*)(rowp + koff);
                    mma16816(acc[nt], a0, a1, a2, a3, b.x, b.y);
                }
            }

            // pass 1: acc -> screened dist in place; partial mins (ILP chains)
            float pA0 = 3.402823466e38f, pA1 = pA0, pB0 = pA0, pB1 = pA0;
#pragma unroll
            for (int nt = 0; nt < 8; ++nt) {
                int cA = cbase + (hlf * 8 + nt) * 8 + q;
                float2 e2 = *(const float2*)&esq_s[cA];
                acc[nt][0] = fmaf(-2.f, acc[nt][0], e2.x);
                acc[nt][1] = fmaf(-2.f, acc[nt][1], e2.y);
                acc[nt][2] = fmaf(-2.f, acc[nt][2], e2.x);
                acc[nt][3] = fmaf(-2.f, acc[nt][3], e2.y);
                if (nt & 1) {
                    pA1 = fminf(pA1, fminf(acc[nt][0], acc[nt][1]));
                    pB1 = fminf(pB1, fminf(acc[nt][2], acc[nt][3]));
                } else {
                    pA0 = fminf(pA0, fminf(acc[nt][0], acc[nt][1]));
                    pB0 = fminf(pB0, fminf(acc[nt][2], acc[nt][3]));
                }
            }
            rmA = fminf(rmA, fminf(pA0, pA1));
            rmB = fminf(rmB, fminf(pB0, pB1));

            // pass 2: push vs FROZEN thresholds (rm includes this half => safe)
            const float thrA = rmA + twoBA;
            const float thrB = rmB + twoBB;
#pragma unroll
            for (int nt = 0; nt < 8; ++nt) {
                int cA = cbase + (hlf * 8 + nt) * 8 + q;
                push_cand2(slotA, cntA, acc[nt][0], thrA, cA);
                push_cand2(slotA, cntA, acc[nt][1], thrA, cA + 1);
                push_cand2(slotB, cntB, acc[nt][2], thrB, cA);
                push_cand2(slotB, cntB, acc[nt][3], thrB, cA + 1);
            }
        }
        __syncthreads();   // buffer reuse
    }

    // ---- per-row screened min (quad reduce) + publish counts ----------------
#pragma unroll
    for (int off = 1; off <= 2; off <<= 1) {
        rmA = fminf(rmA, __shfl_xor_sync(0xffffffffu, rmA, off));
        rmB = fminf(rmB, __shfl_xor_sync(0xffffffffu, rmB, off));
    }
    cnt4_s[r0 * 4 + qd] = (cntA < SLOTS) ? cntA : SLOTS;
    cnt4_s[r1 * 4 + qd] = (cntB < SLOTS) ? cntB : SLOTS;
    if (cntA >= SLOTS) ovf_s[r0] = 1;     // slot (SLOTS-1) may be corrupted
    if (cntB >= SLOTS) ovf_s[r1] = 1;
    if (qd == 0) { rmin_s[r0] = rmA; rmin_s[r1] = rmB; }
    __syncthreads();

    // ---- filter candidates vs row threshold; exact rescore survivors --------
    {
        const int row  = t & 127;
        const int half = t >> 7;
        if (!ovf_s[row]) {
            const float xsq = xsq_s[row];
            const float thr = rmin_s[row] + bnd_s[row] + 16.f + 0.01f;
#pragma unroll
            for (int qq = half * 2; qq < half * 2 + 2; ++qq) {
                int n = cnt4_s[row * 4 + qq];
                const uint32_t* sl = &cand_s[row * ROWSLOT + qq * SLOTS];
                for (int ci = 0; ci < n; ++ci) {
                    uint32_t pk = sl[ci];
                    float scr = __uint_as_float(pk & 0xFFFFFC00u);
                    if (scr <= thr)
                        rescore_one(Xs, row, (int)(pk & 1023u), xsq, esq_s, best_s);
                }
            }
        }
    }
    // overflow rows (rare): full exact rescore by whole CTA
    for (int r = 0; r < MTILE; ++r) {
        if (ovf_s[r]) {
            float xsq = xsq_s[r];
            for (int code = t; code < KCODES; code += THREADS)
                rescore_one(Xs, r, code, xsq, esq_s, best_s);
        }
    }
    __syncthreads();

    if (t < MTILE) {
        int bi = (int)(unsigned)(best_s[t] & 0xFFFFFFFFull);
        idx_out[rowBase + t] = (float)bi;
    }
    __syncthreads();

    // gather winner (coalesced fp32 code-major), write quantized, loss
    float lsum = 0.f;
    const int d = t & 127, half = t >> 7;
    for (int rr = half; rr < MTILE; rr += 2) {
        int bi = (int)(unsigned)(best_s[rr] & 0xFFFFFFFFull);
        float e = __ldg(&g_ET_f32[(size_t)bi * DDIM + d]);
        float x = Xs[rr * XSTRIDE + d];
        q_out[(size_t)(rowBase + rr) * DDIM + d] = e;
        float df = e - x;
        lsum = fmaf(df, df, lsum);
    }
#pragma unroll
    for (int o = 16; o > 0; o >>= 1) lsum += __shfl_xor_sync(0xffffffffu, lsum, o);
    __syncthreads();
    float* rbuf = esq_s;
    if ((t & 31) == 0) rbuf[t >> 5] = lsum;
    __syncthreads();
    if (t == 0) {
        double s = 0.0;
        for (int ww = 0; ww < THREADS / 32; ++ww) s += (double)rbuf[ww];
        atomicAdd(&g_loss_acc, s);
    }
}

// ---- finalize ---------------------------------------------------------------
__global__ void vq_final_kernel(float* loss_out, int numel) {
    loss_out[0] = (float)(0.25 * g_loss_acc / (double)numel);
}

// ----------------------------------------------------------------------------
extern "C" void kernel_launch(void* const* d_in, const int* in_sizes, int n_in,
                              void* d_out, int out_size)
{
    const float* X = (const float*)d_in[0];
    const float* E = (const float*)d_in[1];
    const int N = in_sizes[0] / DDIM;     // 262144

    float* out    = (float*)d_out;
    float* q      = out;
    float* loss_p = out + (size_t)N * DDIM;
    float* idx_p  = out + (size_t)N * DDIM + 1;

    static bool attr_set = false;
    if (!attr_set) {
        cudaFuncSetAttribute(vq_main_kernel,
                             cudaFuncAttributeMaxDynamicSharedMemorySize, SM_TOTAL);
        attr_set = true;
    }

    vq_prep_kernel<<<4, 256>>>(E);
    vq_main_kernel<<<N / MTILE, THREADS, SM_TOTAL>>>(X, q, idx_p);
    vq_final_kernel<<<1, 1>>>(loss_p, N * DDIM);
}